// round 10
// baseline (speedup 1.0000x reference)
#include <cuda_runtime.h>
#include <math_constants.h>
#include <cstdint>

// ---------------- Geometry ----------------
#define MDIM  5184          // 72*72
#define CDIM  256
#define MPAD  5248          // 41*128 (M padded); N exact: 5184 = 81*64
#define NBM   41
#define NBN   81
#define NT    (NBM * NBN)   // 3321 tiles
#define OUT_H 224
#define OUT_W 224
#define QMAX  16255.0f      // 15-bit quant range so hi limb fits s8
#define NCTA  296           // 2 CTAs/SM on 148 SMs -> all co-resident (smem-limited occ 2)
#define NTHR  (NCTA * 256)

// smem stage (BK = 128 bytes of K): A1,A0 128 rows x 128 B; B1,B0 64 rows x 128 B.
// XOR swizzle (chunk' = chunk ^ (row & 7)) -> conflict-free ldmatrix, zero padding.
#define OFF_A1  0
#define OFF_A0  16384
#define OFF_B1  32768
#define OFF_B0  40960
#define STAGE   49152
#define DYN_SMEM (2 * STAGE)          // 98304; whole K=256 in two stages

// ---------------- Device scratch (allocation-free) ----------------
__device__ __align__(16) signed char g_A1[MPAD * CDIM];
__device__ __align__(16) signed char g_A0[MPAD * CDIM];
__device__ __align__(16) signed char g_B1[MPAD * CDIM];
__device__ __align__(16) signed char g_B0[MPAD * CDIM];
__device__ float        g_rpos[MDIM], g_rneg[MDIM], g_cpos[MDIM], g_cneg[MDIM];
__device__ unsigned int g_maxkey;
__device__ unsigned int g_keyA, g_keyB;       // fkey absmax (idempotent across replays)
__device__ unsigned int g_bar, g_depart;      // grid barrier counters (reset in-kernel)
__device__ unsigned int g_tile = NCTA;        // dynamic tile queue (reset in-kernel)

// ---------------- PTX helpers ----------------
__device__ __forceinline__ uint32_t smem_u32(const void* p) {
    uint32_t a;
    asm("{ .reg .u64 t; cvta.to.shared.u64 t, %1; cvt.u32.u64 %0, t; }" : "=r"(a) : "l"(p));
    return a;
}
__device__ __forceinline__ unsigned int fkey(float f) {
    unsigned int u = __float_as_uint(f);
    return (u & 0x80000000u) ? ~u : (u | 0x80000000u);
}
__device__ __forceinline__ float unfkey(unsigned int k) {
    return (k & 0x80000000u) ? __uint_as_float(k & 0x7fffffffu) : __uint_as_float(~k);
}

#define CP16(dst, src) \
    asm volatile("cp.async.cg.shared.global [%0], [%1], 16;" :: "r"(dst), "l"(src))
#define CP_COMMIT()  asm volatile("cp.async.commit_group;")
#define CP_WAIT1()   asm volatile("cp.async.wait_group 1;")
#define CP_WAIT0()   asm volatile("cp.async.wait_group 0;")

#define LDSM4(r0, r1, r2, r3, a) \
    asm volatile("ldmatrix.sync.aligned.m8n8.x4.shared.b16 {%0,%1,%2,%3}, [%4];" \
                 : "=r"(r0), "=r"(r1), "=r"(r2), "=r"(r3) : "r"(a))

#define IMMA(d, a, b) \
    asm volatile("mma.sync.aligned.m16n8k32.row.col.s32.s8.s8.s32 " \
                 "{%0,%1,%2,%3}, {%4,%5,%6,%7}, {%8,%9}, {%0,%1,%2,%3};" \
                 : "+r"((d)[0]), "+r"((d)[1]), "+r"((d)[2]), "+r"((d)[3]) \
                 : "r"((a)[0]), "r"((a)[1]), "r"((a)[2]), "r"((a)[3]), \
                   "r"((b)[0]), "r"((b)[1]))

// Grid-wide barrier: safe because all NCTA blocks are co-resident by construction.
// Read-path polling (volatile LDG + nanosleep), not atomic-RMW spin.
__device__ __forceinline__ void gbar(unsigned target) {
    __syncthreads();
    if (threadIdx.x == 0) {
        __threadfence();
        atomicAdd(&g_bar, 1u);
        while (*(volatile unsigned*)&g_bar < target) __nanosleep(64);
    }
    __syncthreads();
    __threadfence();
}

// Stage load: 3072 CP16 = 12 per thread. Swizzled dst: chunk' = chunk ^ (row & 7).
__device__ __forceinline__ void load_stage(uint32_t sb, const signed char* A1s, const signed char* A0s,
                                           const signed char* B1s, const signed char* B0s,
                                           int kc, int tid) {
    #pragma unroll
    for (int i = 0; i < 12; i++) {
        int idx = tid + i * 256;                 // 0..3071
        const signed char* src;
        uint32_t off;
        int r, q;
        if (idx < 2048) {                        // A1 (0..1023), A0 (1024..2047)
            int w = idx & 1023;
            r = w >> 3; q = w & 7;
            src = (idx < 1024) ? A1s : A0s;
            off = (idx < 1024) ? OFF_A1 : OFF_A0;
        } else {                                 // B1, B0: 64 rows x 8 chunks each
            int w = idx - 2048;
            int ww = w & 511;
            r = ww >> 3; q = ww & 7;
            src = (w < 512) ? B1s : B0s;
            off = (w < 512) ? OFF_B1 : OFF_B0;
        }
        uint32_t dst = sb + off + (uint32_t)(r * 128 + ((q ^ (r & 7)) * 16));
        CP16(dst, src + (size_t)r * CDIM + kc * 128 + q * 16);
    }
}

// ================= The single persistent mega-kernel =================
__global__ __launch_bounds__(256, 2) void simcam_all(const float* __restrict__ x,
                                                     float* __restrict__ out, int total) {
    extern __shared__ unsigned char dsm[];
    __shared__ float s_rp[128], s_rn[128], s_cp[64], s_cn[64], s_wmax[8];
    __shared__ int   s_next;

    const int tid  = threadIdx.x;
    const int gtid = blockIdx.x * 256 + tid;

    // ---------------- Phase A: zero reductions/pads + per-tensor absmax ----------------
    {
        if (gtid < MDIM) { g_rpos[gtid] = 0.f; g_rneg[gtid] = 0.f; g_cpos[gtid] = 0.f; g_cneg[gtid] = 0.f; }
        if (gtid == 0) g_maxkey = 0u;
        if (gtid < 2048) {   // A-plane pad rows [5184,5248): 1024 uint4 each
            const uint4 z = make_uint4(0u, 0u, 0u, 0u);
            signed char* p = (gtid < 1024) ? g_A1 : g_A0;
            ((uint4*)(p + (size_t)MDIM * CDIM))[gtid & 1023] = z;
        }
        float ma = 0.f, mb = 0.f;
        for (int i = gtid; i < MDIM * CDIM / 4; i += NTHR) {
            float4 va = ((const float4*)x)[i];
            float4 vb = ((const float4*)(x + (size_t)MDIM * CDIM))[i];
            ma = fmaxf(ma, fmaxf(fmaxf(fabsf(va.x), fabsf(va.y)), fmaxf(fabsf(va.z), fabsf(va.w))));
            mb = fmaxf(mb, fmaxf(fmaxf(fabsf(vb.x), fabsf(vb.y)), fmaxf(fabsf(vb.z), fabsf(vb.w))));
        }
        #pragma unroll
        for (int off = 16; off; off >>= 1) {
            ma = fmaxf(ma, __shfl_xor_sync(0xffffffffu, ma, off));
            mb = fmaxf(mb, __shfl_xor_sync(0xffffffffu, mb, off));
        }
        if ((tid & 31) == 0) {
            atomicMax(&g_keyA, fkey(ma));    // idempotent across graph replays
            atomicMax(&g_keyB, fkey(mb));
        }
    }
    gbar(NCTA);

    // ---------------- Phase B: quantize V = round(x*QMAX/amax); V = 128*hi + lo ----------------
    {
        const float amaxA = unfkey(g_keyA), amaxB = unfkey(g_keyB);
        const float invA = (amaxA > 0.f) ? (QMAX / amaxA) : 0.f;
        const float invB = (amaxB > 0.f) ? (QMAX / amaxB) : 0.f;
        for (int id = gtid; id < 2 * MDIM * 64; id += NTHR) {
            int op  = id >= MDIM * 64;
            int rid = op ? id - MDIM * 64 : id;
            float inv = op ? invB : invA;
            float4 v = ((const float4*)(x + (size_t)op * MDIM * CDIM))[rid];
            int V[4] = { (int)rintf(v.x * inv), (int)rintf(v.y * inv),
                         (int)rintf(v.z * inv), (int)rintf(v.w * inv) };
            unsigned int p1 = 0, p0 = 0;
            #pragma unroll
            for (int j = 0; j < 4; j++) {
                int hi = (V[j] + 64) >> 7;          // [-127,127]
                int lo = V[j] - (hi << 7);          // [-64,63]
                p1 |= ((unsigned)(hi & 0xFF)) << (8 * j);
                p0 |= ((unsigned)(lo & 0xFF)) << (8 * j);
            }
            ((unsigned int*)(op ? g_B1 : g_A1))[rid] = p1;
            ((unsigned int*)(op ? g_B0 : g_A0))[rid] = p0;
        }
    }
    gbar(2 * NCTA);

    // ---------------- Phase C: dynamic-queue int8 GEMM + fused reductions ----------------
    {
        const int wid  = tid >> 5, lane = tid & 31;
        const int wm   = wid & 3, wn = wid >> 2;     // 4x2 warp grid; warp tile 32x32
        const uint32_t dyn = smem_u32(dsm);
        const uint32_t arow = (uint32_t)((wm * 32 + (lane & 15)) * 128);
        const uint32_t brow = (uint32_t)((wn * 32 + (lane & 15)) * 128);
        const int      cx   = lane >> 4;
        const int      swz  = lane & 7;

        int cur = blockIdx.x;                        // first tile; then atomic queue
        {   // prologue: both stages of first tile in flight
            int bm = cur / NBN, bn = cur % NBN;
            const signed char* A1s = g_A1 + (size_t)bm * 128 * CDIM;
            const signed char* A0s = g_A0 + (size_t)bm * 128 * CDIM;
            const signed char* B1s = g_B1 + (size_t)bn * 64 * CDIM;
            const signed char* B0s = g_B0 + (size_t)bn * 64 * CDIM;
            load_stage(dyn, A1s, A0s, B1s, B0s, 0, tid);
            CP_COMMIT();
            load_stage(dyn + STAGE, A1s, A0s, B1s, B0s, 1, tid);
            CP_COMMIT();
        }

        #pragma unroll 1
        while (cur < NT) {
            const int bm = cur / NBN;

            int acc11[2][4][4], accX[2][4][4];
            #pragma unroll
            for (int mi = 0; mi < 2; mi++)
                #pragma unroll
                for (int nf = 0; nf < 4; nf++)
                    #pragma unroll
                    for (int r = 0; r < 4; r++) { acc11[mi][nf][r] = 0; accX[mi][nf][r] = 0; }

            CP_WAIT1();
            __syncthreads();                          // S1: stage0 ready; prev flush done
            if (tid < 128) { s_rp[tid] = 0.f; s_rn[tid] = 0.f; }
            if (tid < 64)  { s_cp[tid] = 0.f; s_cn[tid] = 0.f; }
            if (tid == 0)  s_next = (int)atomicAdd(&g_tile, 1u);

            // compute kc=0 from buf0
            #pragma unroll
            for (int s = 0; s < 4; s++) {
                const uint32_t ca = (uint32_t)(((2 * s + cx) ^ swz) << 4);
                uint32_t a1[2][4], a0[2][4], b1[4][2], b0[4][2];
                #pragma unroll
                for (int mi = 0; mi < 2; mi++) {
                    LDSM4(a1[mi][0], a1[mi][1], a1[mi][2], a1[mi][3], dyn + OFF_A1 + arow + mi * 2048 + ca);
                    LDSM4(a0[mi][0], a0[mi][1], a0[mi][2], a0[mi][3], dyn + OFF_A0 + arow + mi * 2048 + ca);
                }
                #pragma unroll
                for (int g = 0; g < 2; g++) {
                    uint32_t r0, r1, r2, r3;
                    LDSM4(r0, r1, r2, r3, dyn + OFF_B1 + brow + g * 2048 + ca);
                    b1[2 * g][0] = r0; b1[2 * g][1] = r2; b1[2 * g + 1][0] = r1; b1[2 * g + 1][1] = r3;
                    LDSM4(r0, r1, r2, r3, dyn + OFF_B0 + brow + g * 2048 + ca);
                    b0[2 * g][0] = r0; b0[2 * g][1] = r2; b0[2 * g + 1][0] = r1; b0[2 * g + 1][1] = r3;
                }
                #pragma unroll
                for (int mi = 0; mi < 2; mi++)
                    #pragma unroll
                    for (int nf = 0; nf < 4; nf++) IMMA(acc11[mi][nf], a1[mi], b1[nf]);
                #pragma unroll
                for (int mi = 0; mi < 2; mi++)
                    #pragma unroll
                    for (int nf = 0; nf < 4; nf++) IMMA(accX[mi][nf], a1[mi], b0[nf]);
                #pragma unroll
                for (int mi = 0; mi < 2; mi++)
                    #pragma unroll
                    for (int nf = 0; nf < 4; nf++) IMMA(accX[mi][nf], a0[mi], b1[nf]);
            }

            CP_WAIT0();
            __syncthreads();                          // S2: stage1 ready; buf0 free; s_next visible
            const int nxt = s_next;

            if (nxt < NT) {                           // prefetch next tile stage0 into buf0
                int nbm = nxt / NBN, nbn = nxt % NBN;
                load_stage(dyn,
                           g_A1 + (size_t)nbm * 128 * CDIM, g_A0 + (size_t)nbm * 128 * CDIM,
                           g_B1 + (size_t)nbn * 64 * CDIM,  g_B0 + (size_t)nbn * 64 * CDIM, 0, tid);
                CP_COMMIT();
            }

            // compute kc=1 from buf1
            #pragma unroll
            for (int s = 0; s < 4; s++) {
                const uint32_t ca = (uint32_t)(((2 * s + cx) ^ swz) << 4);
                const uint32_t base = dyn + STAGE;
                uint32_t a1[2][4], a0[2][4], b1[4][2], b0[4][2];
                #pragma unroll
                for (int mi = 0; mi < 2; mi++) {
                    LDSM4(a1[mi][0], a1[mi][1], a1[mi][2], a1[mi][3], base + OFF_A1 + arow + mi * 2048 + ca);
                    LDSM4(a0[mi][0], a0[mi][1], a0[mi][2], a0[mi][3], base + OFF_A0 + arow + mi * 2048 + ca);
                }
                #pragma unroll
                for (int g = 0; g < 2; g++) {
                    uint32_t r0, r1, r2, r3;
                    LDSM4(r0, r1, r2, r3, base + OFF_B1 + brow + g * 2048 + ca);
                    b1[2 * g][0] = r0; b1[2 * g][1] = r2; b1[2 * g + 1][0] = r1; b1[2 * g + 1][1] = r3;
                    LDSM4(r0, r1, r2, r3, base + OFF_B0 + brow + g * 2048 + ca);
                    b0[2 * g][0] = r0; b0[2 * g][1] = r2; b0[2 * g + 1][0] = r1; b0[2 * g + 1][1] = r3;
                }
                #pragma unroll
                for (int mi = 0; mi < 2; mi++)
                    #pragma unroll
                    for (int nf = 0; nf < 4; nf++) IMMA(acc11[mi][nf], a1[mi], b1[nf]);
                #pragma unroll
                for (int mi = 0; mi < 2; mi++)
                    #pragma unroll
                    for (int nf = 0; nf < 4; nf++) IMMA(accX[mi][nf], a1[mi], b0[nf]);
                #pragma unroll
                for (int mi = 0; mi < 2; mi++)
                    #pragma unroll
                    for (int nf = 0; nf < 4; nf++) IMMA(accX[mi][nf], a0[mi], b1[nf]);
            }

            // ---- Fused epilogue part 1: per-warp reductions into shared ----
            float tmax = -CUDART_INF_F;
            const bool tmax_ok = (bm < NBM - 1) || (wm < 2);
            #pragma unroll
            for (int mi = 0; mi < 2; mi++) {
                #pragma unroll
                for (int h = 0; h < 2; h++) {
                    float rp = 0.f, rn = 0.f;
                    #pragma unroll
                    for (int nf = 0; nf < 4; nf++) {
                        float v0 = (float)acc11[mi][nf][2 * h] * 16384.f + (float)accX[mi][nf][2 * h] * 128.f;
                        float v1 = (float)acc11[mi][nf][2 * h + 1] * 16384.f + (float)accX[mi][nf][2 * h + 1] * 128.f;
                        rp += fmaxf(v0, 0.f) + fmaxf(v1, 0.f);
                        rn += fmaxf(-v0, 0.f) + fmaxf(-v1, 0.f);
                        tmax = fmaxf(tmax, fmaxf(v0, v1));
                    }
                    rp += __shfl_xor_sync(0xffffffffu, rp, 1); rp += __shfl_xor_sync(0xffffffffu, rp, 2);
                    rn += __shfl_xor_sync(0xffffffffu, rn, 1); rn += __shfl_xor_sync(0xffffffffu, rn, 2);
                    if ((lane & 3) == 0) {
                        int r = wm * 32 + mi * 16 + (lane >> 2) + h * 8;
                        atomicAdd(&s_rp[r], rp);
                        atomicAdd(&s_rn[r], rn);
                    }
                }
            }
            #pragma unroll
            for (int nf = 0; nf < 4; nf++) {
                #pragma unroll
                for (int j = 0; j < 2; j++) {
                    float cp = 0.f, cn = 0.f;
                    #pragma unroll
                    for (int mi = 0; mi < 2; mi++) {
                        float v0 = (float)acc11[mi][nf][j] * 16384.f + (float)accX[mi][nf][j] * 128.f;
                        float v1 = (float)acc11[mi][nf][j + 2] * 16384.f + (float)accX[mi][nf][j + 2] * 128.f;
                        cp += fmaxf(v0, 0.f) + fmaxf(v1, 0.f);
                        cn += fmaxf(-v0, 0.f) + fmaxf(-v1, 0.f);
                    }
                    cp += __shfl_xor_sync(0xffffffffu, cp, 4);
                    cp += __shfl_xor_sync(0xffffffffu, cp, 8);
                    cp += __shfl_xor_sync(0xffffffffu, cp, 16);
                    cn += __shfl_xor_sync(0xffffffffu, cn, 4);
                    cn += __shfl_xor_sync(0xffffffffu, cn, 8);
                    cn += __shfl_xor_sync(0xffffffffu, cn, 16);
                    if (lane < 4) {
                        int c = wn * 32 + nf * 8 + lane * 2 + j;
                        atomicAdd(&s_cp[c], cp);
                        atomicAdd(&s_cn[c], cn);
                    }
                }
            }
            if (!tmax_ok) tmax = -CUDART_INF_F;
            #pragma unroll
            for (int off = 16; off; off >>= 1)
                tmax = fmaxf(tmax, __shfl_xor_sync(0xffffffffu, tmax, off));
            if (lane == 0) s_wmax[wid] = tmax;
            __syncthreads();                          // S3: buf1 free; s_* complete

            if (nxt < NT) {                           // prefetch next tile stage1 into buf1
                int nbm = nxt / NBN, nbn = nxt % NBN;
                load_stage(dyn + STAGE,
                           g_A1 + (size_t)nbm * 128 * CDIM, g_A0 + (size_t)nbm * 128 * CDIM,
                           g_B1 + (size_t)nbn * 64 * CDIM,  g_B0 + (size_t)nbn * 64 * CDIM, 1, tid);
                CP_COMMIT();
            }

            // ---- Epilogue part 2: flush to global ----
            if (tid < 128) {
                int gr = bm * 128 + tid;
                if (gr < MDIM) { atomicAdd(&g_rpos[gr], s_rp[tid]); atomicAdd(&g_rneg[gr], s_rn[tid]); }
            }
            if (tid < 64) {
                int bn = cur % NBN;
                atomicAdd(&g_cpos[bn * 64 + tid], s_cp[tid]);
                atomicAdd(&g_cneg[bn * 64 + tid], s_cn[tid]);
            }
            if (tid == 0) {
                float bmax = s_wmax[0];
                #pragma unroll
                for (int w = 1; w < 8; w++) bmax = fmaxf(bmax, s_wmax[w]);
                atomicMax(&g_maxkey, fkey(bmax));
            }
            cur = nxt;
        }
    }
    gbar(3 * NCTA);

    // ---------------- Phase D: bilinear resize, all CTAs cooperating ----------------
    {
        float Mv = unfkey(g_maxkey);
        for (int idx = gtid; idx < total; idx += NTHR) {
            int p   = idx / (OUT_H * OUT_W);
            int rem = idx % (OUT_H * OUT_W);
            int oy  = rem / OUT_W;
            int ox  = rem % OUT_W;
            const float* src;
            float inv;
            if (Mv > 0.f)      { src = (p == 0) ? g_rpos : g_cpos; inv =  1.0f / Mv; }
            else if (Mv < 0.f) { src = (p == 0) ? g_rneg : g_cneg; inv = -1.0f / Mv; }
            else               { src = (p == 0) ? g_rpos : g_cpos; inv = 0.0f; }
            const float s = 72.0f / 224.0f;
            float ys = fmaxf(((float)oy + 0.5f) * s - 0.5f, 0.0f);
            float xs = fmaxf(((float)ox + 0.5f) * s - 0.5f, 0.0f);
            int y0 = (int)floorf(ys), x0 = (int)floorf(xs);
            int y1 = min(y0 + 1, 71), x1 = min(x0 + 1, 71);
            float wy = ys - (float)y0, wx = xs - (float)x0;
            float a = src[y0 * 72 + x0], b = src[y0 * 72 + x1];
            float c = src[y1 * 72 + x0], d = src[y1 * 72 + x1];
            out[idx] = (a * (1.f - wy) * (1.f - wx) + b * (1.f - wy) * wx
                      + c * wy * (1.f - wx)         + d * wy * wx) * inv;
        }
    }

    // ---------------- Exit protocol: reset counters for the next replay ----------------
    __syncthreads();
    if (tid == 0) {
        __threadfence();
        atomicAdd(&g_depart, 1u);
        if (blockIdx.x == 0) {
            while (*(volatile unsigned*)&g_depart < NCTA) __nanosleep(64);
            g_bar = 0u; g_depart = 0u; g_tile = NCTA;
            __threadfence();
        }
    }
}

extern "C" void kernel_launch(void* const* d_in, const int* in_sizes, int n_in,
                              void* d_out, int out_size) {
    const float* x = (const float*)d_in[0];   // (2,72,72,256) fp32
    cudaFuncSetAttribute(simcam_all, cudaFuncAttributeMaxDynamicSharedMemorySize, DYN_SMEM);
    simcam_all<<<NCTA, 256, DYN_SMEM>>>(x, (float*)d_out, out_size);
}

// round 11
// speedup vs baseline: 1.0648x; 1.0648x over previous
#include <cuda_runtime.h>
#include <math_constants.h>
#include <cstdint>

// ---------------- Geometry ----------------
#define MDIM  5184          // 72*72
#define CDIM  256
#define MPAD  5248          // 41*128 (M padded); N exact: 5184 = 81*64
#define NBM   41            // M tiles of 128 (last tile half pad)
#define NBN   81            // N tiles of 64, exact
#define OUT_H 224
#define OUT_W 224
#define QMAX  16255.0f      // 15-bit quant range so hi limb fits s8
#define NPREP 1184          // prep grid: 8 blocks/SM (2048 thr) -> co-resident, barrier-safe

// smem stage (BK = 128 bytes of K): A1,A0 128 rows x 128 B; B1,B0 64 rows x 128 B.
// XOR swizzle (chunk' = chunk ^ (row & 7)) -> conflict-free ldmatrix, zero padding.
#define OFF_A1  0
#define OFF_A0  16384
#define OFF_B1  32768
#define OFF_B0  40960
#define STAGE   49152
#define DYN_SMEM (2 * STAGE)          // 98304; whole K=256 in two stages

// ---------------- Device scratch (allocation-free) ----------------
__device__ __align__(16) signed char g_A1[MPAD * CDIM];   // hi limbs
__device__ __align__(16) signed char g_A0[MPAD * CDIM];
__device__ __align__(16) signed char g_B1[MPAD * CDIM];
__device__ __align__(16) signed char g_B0[MPAD * CDIM];
__device__ float        g_rpos[MDIM], g_rneg[MDIM], g_cpos[MDIM], g_cneg[MDIM];
__device__ unsigned int g_maxkey;
__device__ unsigned int g_keyA, g_keyB;     // fkey-encoded absmax (idempotent across runs)
__device__ unsigned int g_ctr;              // prep barrier counter (reset by resize each run)

// ---------------- PTX helpers ----------------
__device__ __forceinline__ uint32_t smem_u32(const void* p) {
    uint32_t a;
    asm("{ .reg .u64 t; cvta.to.shared.u64 t, %1; cvt.u32.u64 %0, t; }" : "=r"(a) : "l"(p));
    return a;
}
__device__ __forceinline__ unsigned int fkey(float f) {
    unsigned int u = __float_as_uint(f);
    return (u & 0x80000000u) ? ~u : (u | 0x80000000u);
}
__device__ __forceinline__ float unfkey(unsigned int k) {
    return (k & 0x80000000u) ? __uint_as_float(k & 0x7fffffffu) : __uint_as_float(~k);
}

#define CP16(dst, src) \
    asm volatile("cp.async.cg.shared.global [%0], [%1], 16;" :: "r"(dst), "l"(src))
#define CP_COMMIT()  asm volatile("cp.async.commit_group;")
#define CP_WAIT1()   asm volatile("cp.async.wait_group 1;")
#define CP_WAIT0()   asm volatile("cp.async.wait_group 0;")

#define LDSM4(r0, r1, r2, r3, a) \
    asm volatile("ldmatrix.sync.aligned.m8n8.x4.shared.b16 {%0,%1,%2,%3}, [%4];" \
                 : "=r"(r0), "=r"(r1), "=r"(r2), "=r"(r3) : "r"(a))

#define IMMA(d, a, b) \
    asm volatile("mma.sync.aligned.m16n8k32.row.col.s32.s8.s8.s32 " \
                 "{%0,%1,%2,%3}, {%4,%5,%6,%7}, {%8,%9}, {%0,%1,%2,%3};" \
                 : "+r"((d)[0]), "+r"((d)[1]), "+r"((d)[2]), "+r"((d)[3]) \
                 : "r"((a)[0]), "r"((a)[1]), "r"((a)[2]), "r"((a)[3]), \
                   "r"((b)[0]), "r"((b)[1]))

// ---------------- Kernels ----------------

// Fused prep: absmax + zeroing, device-wide barrier, then quantize.
// 1184 blocks x 256 = 8 blocks/SM, full occupancy, co-resident -> spin barrier is safe.
__global__ __launch_bounds__(256) void simcam_prep(const float* __restrict__ x) {
    const int gtid = blockIdx.x * blockDim.x + threadIdx.x;
    const int nthr = NPREP * 256;

    // ---- Phase 1: zero reductions + A-plane pad rows; partial absmax ----
    if (gtid < MDIM) { g_rpos[gtid] = 0.f; g_rneg[gtid] = 0.f; g_cpos[gtid] = 0.f; g_cneg[gtid] = 0.f; }
    if (gtid == 0) g_maxkey = 0u;
    if (gtid < 2048) {   // pad rows [5184,5248) x 256 B x 2 A-planes = 2048 uint4
        const uint4 z = make_uint4(0u, 0u, 0u, 0u);
        signed char* p = (gtid < 1024) ? g_A1 : g_A0;
        ((uint4*)(p + (size_t)MDIM * CDIM))[gtid & 1023] = z;
    }
    float ma = 0.f, mb = 0.f;
    for (int i = gtid; i < MDIM * CDIM / 4; i += nthr) {
        float4 va = ((const float4*)x)[i];
        float4 vb = ((const float4*)(x + (size_t)MDIM * CDIM))[i];
        ma = fmaxf(ma, fmaxf(fmaxf(fabsf(va.x), fabsf(va.y)), fmaxf(fabsf(va.z), fabsf(va.w))));
        mb = fmaxf(mb, fmaxf(fmaxf(fabsf(vb.x), fabsf(vb.y)), fmaxf(fabsf(vb.z), fabsf(vb.w))));
    }
    #pragma unroll
    for (int off = 16; off; off >>= 1) {
        ma = fmaxf(ma, __shfl_xor_sync(0xffffffffu, ma, off));
        mb = fmaxf(mb, __shfl_xor_sync(0xffffffffu, mb, off));
    }
    if ((threadIdx.x & 31) == 0) {
        atomicMax(&g_keyA, fkey(ma));    // idempotent across graph replays
        atomicMax(&g_keyB, fkey(mb));
    }

    // ---- Device-wide barrier (all 1184 blocks co-resident) ----
    // One RMW per block; polling is a volatile LOAD (L2 read path, no atomic-ALU contention).
    __threadfence();
    __syncthreads();
    if (threadIdx.x == 0) {
        atomicAdd(&g_ctr, 1u);
        while (*(volatile unsigned*)&g_ctr < NPREP) __nanosleep(64);
    }
    __syncthreads();
    __threadfence();

    // ---- Phase 2: quantize V = round(x*QMAX/absmax), split V = 128*hi + lo ----
    const float amaxA = unfkey(g_keyA), amaxB = unfkey(g_keyB);
    const float invA = (amaxA > 0.f) ? (QMAX / amaxA) : 0.f;
    const float invB = (amaxB > 0.f) ? (QMAX / amaxB) : 0.f;
    for (int id = gtid; id < 2 * MDIM * 64; id += nthr) {
        int op  = id >= MDIM * 64;
        int rid = op ? id - MDIM * 64 : id;
        float inv = op ? invB : invA;
        float4 v = ((const float4*)(x + (size_t)op * MDIM * CDIM))[rid];
        int V[4] = { (int)rintf(v.x * inv), (int)rintf(v.y * inv),
                     (int)rintf(v.z * inv), (int)rintf(v.w * inv) };
        unsigned int p1 = 0, p0 = 0;
        #pragma unroll
        for (int j = 0; j < 4; j++) {
            int hi = (V[j] + 64) >> 7;          // [-127,127]
            int lo = V[j] - (hi << 7);          // [-64,63]
            p1 |= ((unsigned)(hi & 0xFF)) << (8 * j);
            p0 |= ((unsigned)(lo & 0xFF)) << (8 * j);
        }
        ((unsigned int*)(op ? g_B1 : g_A1))[rid] = p1;
        ((unsigned int*)(op ? g_B0 : g_A0))[rid] = p0;
    }
}

// Stage load: 3072 CP16 = 12 per thread. Swizzled dst: chunk' = chunk ^ (row & 7).
__device__ __forceinline__ void load_stage(uint32_t sb, const signed char* A1s, const signed char* A0s,
                                           const signed char* B1s, const signed char* B0s,
                                           int kc, int tid) {
    #pragma unroll
    for (int i = 0; i < 12; i++) {
        int idx = tid + i * 256;                 // 0..3071
        const signed char* src;
        uint32_t off;
        int r, q;
        if (idx < 2048) {                        // A1 (0..1023), A0 (1024..2047): 128 rows x 8 chunks
            int w = idx & 1023;
            r = w >> 3; q = w & 7;
            src = (idx < 1024) ? A1s : A0s;
            off = (idx < 1024) ? OFF_A1 : OFF_A0;
        } else {                                 // B1, B0: 64 rows x 8 chunks each
            int w = idx - 2048;
            int ww = w & 511;
            r = ww >> 3; q = ww & 7;
            src = (w < 512) ? B1s : B0s;
            off = (w < 512) ? OFF_B1 : OFF_B0;
        }
        uint32_t dst = sb + off + (uint32_t)(r * 128 + ((q ^ (r & 7)) * 16));
        CP16(dst, src + (size_t)r * CDIM + kc * 128 + q * 16);
    }
}

// Fused int8 GEMM: d ~ 16384*(A1 B1) + 128*(A1 B0 + A0 B1) per 128x64 tile,
// + relu row/col sums + global max (scale cancels in final ratio).
__global__ __launch_bounds__(256, 2) void simcam_gemm() {
    extern __shared__ unsigned char dsm[];
    __shared__ float s_rp[128], s_rn[128], s_cp[64], s_cn[64], s_wmax[8];

    const int tid  = threadIdx.x;
    const int wid  = tid >> 5, lane = tid & 31;
    const int wm   = wid & 3, wn = wid >> 2;     // 4x2 warp grid; warp tile 32(M) x 32(N)
    const int bm   = blockIdx.y, bn = blockIdx.x;

    if (tid < 128) { s_rp[tid] = 0.f; s_rn[tid] = 0.f; }
    if (tid < 64)  { s_cp[tid] = 0.f; s_cn[tid] = 0.f; }

    const signed char* A1s = g_A1 + (size_t)bm * 128 * CDIM;
    const signed char* A0s = g_A0 + (size_t)bm * 128 * CDIM;
    const signed char* B1s = g_B1 + (size_t)bn * 64 * CDIM;
    const signed char* B0s = g_B0 + (size_t)bn * 64 * CDIM;
    const uint32_t dyn = smem_u32(dsm);

    // ldmatrix lane addressing (16 rows x two 16B chunk-slots, swizzled per row)
    const uint32_t arow = (uint32_t)((wm * 32 + (lane & 15)) * 128);
    const uint32_t brow = (uint32_t)((wn * 32 + (lane & 15)) * 128);
    const int      cx   = lane >> 4;             // chunk slot 0/1
    const int      swz  = lane & 7;              // row-dependent XOR key

    int acc11[2][4][4], accX[2][4][4];
    #pragma unroll
    for (int mi = 0; mi < 2; mi++)
        #pragma unroll
        for (int nf = 0; nf < 4; nf++)
            #pragma unroll
            for (int r = 0; r < 4; r++) { acc11[mi][nf][r] = 0; accX[mi][nf][r] = 0; }

    // Issue BOTH stages (whole K) up front; stage1 streams in behind stage0's compute.
    load_stage(dyn + 0 * STAGE, A1s, A0s, B1s, B0s, 0, tid);
    CP_COMMIT();
    load_stage(dyn + 1 * STAGE, A1s, A0s, B1s, B0s, 1, tid);
    CP_COMMIT();

    #pragma unroll
    for (int kc = 0; kc < 2; kc++) {
        if (kc == 0) CP_WAIT1(); else CP_WAIT0();
        __syncthreads();
        const uint32_t base = dyn + kc * STAGE;
        #pragma unroll
        for (int s = 0; s < 4; s++) {            // four k32 sub-chunks of 128 bytes
            const uint32_t ca = (uint32_t)(((2 * s + cx) ^ swz) << 4);
            uint32_t a1[2][4], a0[2][4], b1[4][2], b0[4][2];
            #pragma unroll
            for (int mi = 0; mi < 2; mi++) {
                LDSM4(a1[mi][0], a1[mi][1], a1[mi][2], a1[mi][3],
                      base + OFF_A1 + arow + mi * 2048 + ca);
                LDSM4(a0[mi][0], a0[mi][1], a0[mi][2], a0[mi][3],
                      base + OFF_A0 + arow + mi * 2048 + ca);
            }
            #pragma unroll
            for (int g = 0; g < 2; g++) {
                uint32_t r0, r1, r2, r3;
                LDSM4(r0, r1, r2, r3, base + OFF_B1 + brow + g * 2048 + ca);
                b1[2 * g][0] = r0; b1[2 * g][1] = r2;
                b1[2 * g + 1][0] = r1; b1[2 * g + 1][1] = r3;
                LDSM4(r0, r1, r2, r3, base + OFF_B0 + brow + g * 2048 + ca);
                b0[2 * g][0] = r0; b0[2 * g][1] = r2;
                b0[2 * g + 1][0] = r1; b0[2 * g + 1][1] = r3;
            }
            #pragma unroll
            for (int mi = 0; mi < 2; mi++)
                #pragma unroll
                for (int nf = 0; nf < 4; nf++) IMMA(acc11[mi][nf], a1[mi], b1[nf]);
            #pragma unroll
            for (int mi = 0; mi < 2; mi++)
                #pragma unroll
                for (int nf = 0; nf < 4; nf++) IMMA(accX[mi][nf], a1[mi], b0[nf]);
            #pragma unroll
            for (int mi = 0; mi < 2; mi++)
                #pragma unroll
                for (int nf = 0; nf < 4; nf++) IMMA(accX[mi][nf], a0[mi], b1[nf]);
        }
    }

    // ---- Fused epilogue, de-predicated ----
    // All columns valid (NBN exact). Pad rows hold exact zeros -> contribute 0 to all
    // sums; row validity uniform per warp: invalid only when bm==NBM-1 && wm>=2.
    float tmax = -CUDART_INF_F;
    const bool tmax_ok = (bm < NBM - 1) || (wm < 2);

    #pragma unroll
    for (int mi = 0; mi < 2; mi++) {
        #pragma unroll
        for (int h = 0; h < 2; h++) {
            float rp = 0.f, rn = 0.f;
            #pragma unroll
            for (int nf = 0; nf < 4; nf++) {
                float v0 = (float)acc11[mi][nf][2 * h] * 16384.f + (float)accX[mi][nf][2 * h] * 128.f;
                float v1 = (float)acc11[mi][nf][2 * h + 1] * 16384.f + (float)accX[mi][nf][2 * h + 1] * 128.f;
                rp += fmaxf(v0, 0.f) + fmaxf(v1, 0.f);
                rn += fmaxf(-v0, 0.f) + fmaxf(-v1, 0.f);
                tmax = fmaxf(tmax, fmaxf(v0, v1));
            }
            rp += __shfl_xor_sync(0xffffffffu, rp, 1); rp += __shfl_xor_sync(0xffffffffu, rp, 2);
            rn += __shfl_xor_sync(0xffffffffu, rn, 1); rn += __shfl_xor_sync(0xffffffffu, rn, 2);
            if ((lane & 3) == 0) {
                int r = wm * 32 + mi * 16 + (lane >> 2) + h * 8;
                atomicAdd(&s_rp[r], rp);
                atomicAdd(&s_rn[r], rn);
            }
        }
    }
    #pragma unroll
    for (int nf = 0; nf < 4; nf++) {
        #pragma unroll
        for (int j = 0; j < 2; j++) {
            float cp = 0.f, cn = 0.f;
            #pragma unroll
            for (int mi = 0; mi < 2; mi++) {
                float v0 = (float)acc11[mi][nf][j] * 16384.f + (float)accX[mi][nf][j] * 128.f;
                float v1 = (float)acc11[mi][nf][j + 2] * 16384.f + (float)accX[mi][nf][j + 2] * 128.f;
                cp += fmaxf(v0, 0.f) + fmaxf(v1, 0.f);
                cn += fmaxf(-v0, 0.f) + fmaxf(-v1, 0.f);
            }
            cp += __shfl_xor_sync(0xffffffffu, cp, 4);
            cp += __shfl_xor_sync(0xffffffffu, cp, 8);
            cp += __shfl_xor_sync(0xffffffffu, cp, 16);
            cn += __shfl_xor_sync(0xffffffffu, cn, 4);
            cn += __shfl_xor_sync(0xffffffffu, cn, 8);
            cn += __shfl_xor_sync(0xffffffffu, cn, 16);
            if (lane < 4) {
                int c = wn * 32 + nf * 8 + lane * 2 + j;
                atomicAdd(&s_cp[c], cp);
                atomicAdd(&s_cn[c], cn);
            }
        }
    }
    if (!tmax_ok) tmax = -CUDART_INF_F;
    #pragma unroll
    for (int off = 16; off; off >>= 1)
        tmax = fmaxf(tmax, __shfl_xor_sync(0xffffffffu, tmax, off));
    if (lane == 0) s_wmax[wid] = tmax;
    __syncthreads();

    if (tid < 128) {
        int gr = bm * 128 + tid;
        if (gr < MDIM) { atomicAdd(&g_rpos[gr], s_rp[tid]); atomicAdd(&g_rneg[gr], s_rn[tid]); }
    }
    if (tid < 64) {
        atomicAdd(&g_cpos[bn * 64 + tid], s_cp[tid]);
        atomicAdd(&g_cneg[bn * 64 + tid], s_cn[tid]);
    }
    if (tid == 0) {
        float bmax = s_wmax[0];
        #pragma unroll
        for (int w = 1; w < 8; w++) bmax = fmaxf(bmax, s_wmax[w]);
        atomicMax(&g_maxkey, fkey(bmax));
    }
}

// Bilinear resize (align_corners=False) with deferred 1/|M| scale + pos/neg selection.
// Also resets the prep barrier counter for the next graph replay.
__global__ void simcam_resize(float* __restrict__ out, int total) {
    int idx = blockIdx.x * blockDim.x + threadIdx.x;
    if (idx == 0) g_ctr = 0u;
    if (idx >= total) return;
    int p   = idx / (OUT_H * OUT_W);
    int rem = idx % (OUT_H * OUT_W);
    int oy  = rem / OUT_W;
    int ox  = rem % OUT_W;

    float Mv = unfkey(g_maxkey);
    const float* src;
    float inv;
    if (Mv > 0.f)      { src = (p == 0) ? g_rpos : g_cpos; inv =  1.0f / Mv; }
    else if (Mv < 0.f) { src = (p == 0) ? g_rneg : g_cneg; inv = -1.0f / Mv; }
    else               { src = (p == 0) ? g_rpos : g_cpos; inv = 0.0f; }

    const float s = 72.0f / 224.0f;
    float ys = fmaxf(((float)oy + 0.5f) * s - 0.5f, 0.0f);
    float xs = fmaxf(((float)ox + 0.5f) * s - 0.5f, 0.0f);
    int y0 = (int)floorf(ys), x0 = (int)floorf(xs);
    int y1 = min(y0 + 1, 71), x1 = min(x0 + 1, 71);
    float wy = ys - (float)y0, wx = xs - (float)x0;

    float a = src[y0 * 72 + x0], b = src[y0 * 72 + x1];
    float c = src[y1 * 72 + x0], d = src[y1 * 72 + x1];
    out[idx] = (a * (1.f - wy) * (1.f - wx) + b * (1.f - wy) * wx
              + c * wy * (1.f - wx)         + d * wy * wx) * inv;
}

extern "C" void kernel_launch(void* const* d_in, const int* in_sizes, int n_in,
                              void* d_out, int out_size) {
    const float* x = (const float*)d_in[0];   // (2,72,72,256) fp32
    cudaFuncSetAttribute(simcam_gemm, cudaFuncAttributeMaxDynamicSharedMemorySize, DYN_SMEM);

    simcam_prep<<<NPREP, 256>>>(x);
    dim3 grid(NBN, NBM);
    simcam_gemm<<<grid, 256, DYN_SMEM>>>();
    simcam_resize<<<(out_size + 255) / 256, 256>>>((float*)d_out, out_size);
}

// round 12
// speedup vs baseline: 1.1792x; 1.1075x over previous
#include <cuda_runtime.h>
#include <math_constants.h>
#include <cstdint>

// ---------------- Geometry ----------------
#define MDIM  5184          // 72*72
#define CDIM  256
#define MPAD  5248          // 41*128 (M padded); N exact: 5184 = 81*64
#define NBM   41            // M tiles of 128 (last tile half pad)
#define NBN   81            // N tiles of 64, exact
#define OUT_H 224
#define OUT_W 224
#define QMAX  16255.0f      // 15-bit quant range so hi limb fits s8
#define NPREP 592           // prep grid: 4 blocks/SM, co-resident -> spin barrier safe

// smem stage (BK = 128 bytes of K): A1,A0 128 rows x 128 B; B1,B0 64 rows x 128 B.
// XOR swizzle (chunk' = chunk ^ (row & 7)) -> conflict-free ldmatrix, zero padding.
#define OFF_A1  0
#define OFF_A0  16384
#define OFF_B1  32768
#define OFF_B0  40960
#define STAGE   49152
#define DYN_SMEM (2 * STAGE)          // 98304; whole K=256 in two stages

// ---------------- Device scratch (allocation-free) ----------------
__device__ __align__(16) signed char g_A1[MPAD * CDIM];   // hi limbs
__device__ __align__(16) signed char g_A0[MPAD * CDIM];
__device__ __align__(16) signed char g_B1[MPAD * CDIM];
__device__ __align__(16) signed char g_B0[MPAD * CDIM];
__device__ float        g_rpos[MPAD], g_rneg[MPAD];       // MPAD: pad rows take harmless 0-adds
__device__ float        g_cpos[MDIM], g_cneg[MDIM];
__device__ unsigned int g_maxkey;
__device__ unsigned int g_keyA, g_keyB;     // fkey-encoded absmax (idempotent across runs)
__device__ unsigned int g_ctr;              // prep barrier counter (reset by resize each run)

// ---------------- PTX helpers ----------------
__device__ __forceinline__ uint32_t smem_u32(const void* p) {
    uint32_t a;
    asm("{ .reg .u64 t; cvta.to.shared.u64 t, %1; cvt.u32.u64 %0, t; }" : "=r"(a) : "l"(p));
    return a;
}
__device__ __forceinline__ unsigned int fkey(float f) {
    unsigned int u = __float_as_uint(f);
    return (u & 0x80000000u) ? ~u : (u | 0x80000000u);
}
__device__ __forceinline__ float unfkey(unsigned int k) {
    return (k & 0x80000000u) ? __uint_as_float(k & 0x7fffffffu) : __uint_as_float(~k);
}
__device__ __forceinline__ float amax4(float4 v) {
    return fmaxf(fmaxf(fabsf(v.x), fabsf(v.y)), fmaxf(fabsf(v.z), fabsf(v.w)));
}

#define CP16(dst, src) \
    asm volatile("cp.async.cg.shared.global [%0], [%1], 16;" :: "r"(dst), "l"(src))
#define CP_COMMIT()  asm volatile("cp.async.commit_group;")
#define CP_WAIT1()   asm volatile("cp.async.wait_group 1;")
#define CP_WAIT0()   asm volatile("cp.async.wait_group 0;")

#define LDSM4(r0, r1, r2, r3, a) \
    asm volatile("ldmatrix.sync.aligned.m8n8.x4.shared.b16 {%0,%1,%2,%3}, [%4];" \
                 : "=r"(r0), "=r"(r1), "=r"(r2), "=r"(r3) : "r"(a))

#define IMMA(d, a, b) \
    asm volatile("mma.sync.aligned.m16n8k32.row.col.s32.s8.s8.s32 " \
                 "{%0,%1,%2,%3}, {%4,%5,%6,%7}, {%8,%9}, {%0,%1,%2,%3};" \
                 : "+r"((d)[0]), "+r"((d)[1]), "+r"((d)[2]), "+r"((d)[3]) \
                 : "r"((a)[0]), "r"((a)[1]), "r"((a)[2]), "r"((a)[3]), \
                   "r"((b)[0]), "r"((b)[1]))

// ---------------- Kernels ----------------

// Fused prep: absmax + zeroing, device-wide barrier, then quantize.
// 592 blocks x 256 = 4 blocks/SM, co-resident by construction -> spin barrier is safe.
__global__ __launch_bounds__(256) void simcam_prep(const float* __restrict__ x) {
    const int gtid = blockIdx.x * blockDim.x + threadIdx.x;     // 0..151551
    const int nthr = NPREP * 256;

    // ---- Phase 1: zero reductions (MPAD rows) + A-plane pad rows; absmax at MLP 4 ----
    if (gtid < MPAD) { g_rpos[gtid] = 0.f; g_rneg[gtid] = 0.f; }
    if (gtid < MDIM) { g_cpos[gtid] = 0.f; g_cneg[gtid] = 0.f; }
    if (gtid == 0) g_maxkey = 0u;
    if (gtid < 2048) {   // pad rows [5184,5248) x 256 B x 2 A-planes = 2048 uint4
        const uint4 z = make_uint4(0u, 0u, 0u, 0u);
        signed char* p = (gtid < 1024) ? g_A1 : g_A0;
        ((uint4*)(p + (size_t)MDIM * CDIM))[gtid & 1023] = z;
    }
    // 331776 float4 per tensor, 151552 threads: 2 guaranteed iters + 1 conditional.
    const float4* x4a = (const float4*)x;
    const float4* x4b = (const float4*)(x + (size_t)MDIM * CDIM);
    float4 va0 = x4a[gtid], va1 = x4a[gtid + nthr];          // 4 independent loads in flight
    float4 vb0 = x4b[gtid], vb1 = x4b[gtid + nthr];
    float ma = fmaxf(amax4(va0), amax4(va1));
    float mb = fmaxf(amax4(vb0), amax4(vb1));
    if (gtid + 2 * nthr < MDIM * CDIM / 4) {
        ma = fmaxf(ma, amax4(x4a[gtid + 2 * nthr]));
        mb = fmaxf(mb, amax4(x4b[gtid + 2 * nthr]));
    }
    #pragma unroll
    for (int off = 16; off; off >>= 1) {
        ma = fmaxf(ma, __shfl_xor_sync(0xffffffffu, ma, off));
        mb = fmaxf(mb, __shfl_xor_sync(0xffffffffu, mb, off));
    }
    if ((threadIdx.x & 31) == 0) {
        atomicMax(&g_keyA, fkey(ma));    // idempotent across graph replays
        atomicMax(&g_keyB, fkey(mb));
    }

    // ---- Device-wide barrier (all 592 blocks co-resident) ----
    __threadfence();
    __syncthreads();
    if (threadIdx.x == 0) {
        atomicAdd(&g_ctr, 1u);
        while (atomicAdd(&g_ctr, 0u) < NPREP) { }
    }
    __syncthreads();
    __threadfence();

    // ---- Phase 2: quantize V = round(x*QMAX/absmax), split V = 128*hi + lo ----
    const float amaxA = unfkey(g_keyA), amaxB = unfkey(g_keyB);
    const float invA = (amaxA > 0.f) ? (QMAX / amaxA) : 0.f;
    const float invB = (amaxB > 0.f) ? (QMAX / amaxB) : 0.f;
    for (int id = gtid; id < 2 * MDIM * 64; id += nthr) {
        int op  = id >= MDIM * 64;
        int rid = op ? id - MDIM * 64 : id;
        float inv = op ? invB : invA;
        float4 v = ((const float4*)(x + (size_t)op * MDIM * CDIM))[rid];
        int V[4] = { (int)rintf(v.x * inv), (int)rintf(v.y * inv),
                     (int)rintf(v.z * inv), (int)rintf(v.w * inv) };
        unsigned int p1 = 0, p0 = 0;
        #pragma unroll
        for (int j = 0; j < 4; j++) {
            int hi = (V[j] + 64) >> 7;          // [-127,127]
            int lo = V[j] - (hi << 7);          // [-64,63]
            p1 |= ((unsigned)(hi & 0xFF)) << (8 * j);
            p0 |= ((unsigned)(lo & 0xFF)) << (8 * j);
        }
        ((unsigned int*)(op ? g_B1 : g_A1))[rid] = p1;
        ((unsigned int*)(op ? g_B0 : g_A0))[rid] = p0;
    }
}

// Stage load: 3072 CP16 = 12 per thread. Swizzled dst: chunk' = chunk ^ (row & 7).
__device__ __forceinline__ void load_stage(uint32_t sb, const signed char* A1s, const signed char* A0s,
                                           const signed char* B1s, const signed char* B0s,
                                           int kc, int tid) {
    #pragma unroll
    for (int i = 0; i < 12; i++) {
        int idx = tid + i * 256;                 // 0..3071
        const signed char* src;
        uint32_t off;
        int r, q;
        if (idx < 2048) {                        // A1 (0..1023), A0 (1024..2047): 128 rows x 8 chunks
            int w = idx & 1023;
            r = w >> 3; q = w & 7;
            src = (idx < 1024) ? A1s : A0s;
            off = (idx < 1024) ? OFF_A1 : OFF_A0;
        } else {                                 // B1, B0: 64 rows x 8 chunks each
            int w = idx - 2048;
            int ww = w & 511;
            r = ww >> 3; q = ww & 7;
            src = (w < 512) ? B1s : B0s;
            off = (w < 512) ? OFF_B1 : OFF_B0;
        }
        uint32_t dst = sb + off + (uint32_t)(r * 128 + ((q ^ (r & 7)) * 16));
        CP16(dst, src + (size_t)r * CDIM + kc * 128 + q * 16);
    }
}

// Fused int8 GEMM: d ~ 16384*(A1 B1) + 128*(A1 B0 + A0 B1) per 128x64 tile,
// + relu row/col sums + global max (scale cancels in final ratio).
__global__ __launch_bounds__(256, 2) void simcam_gemm() {
    extern __shared__ unsigned char dsm[];
    __shared__ float s_cp[64], s_cn[64], s_wmax[8];

    const int tid  = threadIdx.x;
    const int wid  = tid >> 5, lane = tid & 31;
    const int wm   = wid & 3, wn = wid >> 2;     // 4x2 warp grid; warp tile 32(M) x 32(N)
    const int bm   = blockIdx.y, bn = blockIdx.x;

    if (tid < 64)  { s_cp[tid] = 0.f; s_cn[tid] = 0.f; }

    const signed char* A1s = g_A1 + (size_t)bm * 128 * CDIM;
    const signed char* A0s = g_A0 + (size_t)bm * 128 * CDIM;
    const signed char* B1s = g_B1 + (size_t)bn * 64 * CDIM;
    const signed char* B0s = g_B0 + (size_t)bn * 64 * CDIM;
    const uint32_t dyn = smem_u32(dsm);

    // ldmatrix lane addressing (16 rows x two 16B chunk-slots, swizzled per row)
    const uint32_t arow = (uint32_t)((wm * 32 + (lane & 15)) * 128);
    const uint32_t brow = (uint32_t)((wn * 32 + (lane & 15)) * 128);
    const int      cx   = lane >> 4;             // chunk slot 0/1
    const int      swz  = lane & 7;              // row-dependent XOR key

    int acc11[2][4][4], accX[2][4][4];
    #pragma unroll
    for (int mi = 0; mi < 2; mi++)
        #pragma unroll
        for (int nf = 0; nf < 4; nf++)
            #pragma unroll
            for (int r = 0; r < 4; r++) { acc11[mi][nf][r] = 0; accX[mi][nf][r] = 0; }

    // Issue BOTH stages (whole K) up front; stage1 streams in behind stage0's compute.
    load_stage(dyn + 0 * STAGE, A1s, A0s, B1s, B0s, 0, tid);
    CP_COMMIT();
    load_stage(dyn + 1 * STAGE, A1s, A0s, B1s, B0s, 1, tid);
    CP_COMMIT();

    #pragma unroll
    for (int kc = 0; kc < 2; kc++) {
        if (kc == 0) CP_WAIT1(); else CP_WAIT0();
        __syncthreads();
        const uint32_t base = dyn + kc * STAGE;
        #pragma unroll
        for (int s = 0; s < 4; s++) {            // four k32 sub-chunks of 128 bytes
            const uint32_t ca = (uint32_t)(((2 * s + cx) ^ swz) << 4);
            uint32_t a1[2][4], a0[2][4], b1[4][2], b0[4][2];
            #pragma unroll
            for (int mi = 0; mi < 2; mi++) {
                LDSM4(a1[mi][0], a1[mi][1], a1[mi][2], a1[mi][3],
                      base + OFF_A1 + arow + mi * 2048 + ca);
                LDSM4(a0[mi][0], a0[mi][1], a0[mi][2], a0[mi][3],
                      base + OFF_A0 + arow + mi * 2048 + ca);
            }
            #pragma unroll
            for (int g = 0; g < 2; g++) {
                uint32_t r0, r1, r2, r3;
                LDSM4(r0, r1, r2, r3, base + OFF_B1 + brow + g * 2048 + ca);
                b1[2 * g][0] = r0; b1[2 * g][1] = r2;
                b1[2 * g + 1][0] = r1; b1[2 * g + 1][1] = r3;
                LDSM4(r0, r1, r2, r3, base + OFF_B0 + brow + g * 2048 + ca);
                b0[2 * g][0] = r0; b0[2 * g][1] = r2;
                b0[2 * g + 1][0] = r1; b0[2 * g + 1][1] = r3;
            }
            #pragma unroll
            for (int mi = 0; mi < 2; mi++)
                #pragma unroll
                for (int nf = 0; nf < 4; nf++) IMMA(acc11[mi][nf], a1[mi], b1[nf]);
            #pragma unroll
            for (int mi = 0; mi < 2; mi++)
                #pragma unroll
                for (int nf = 0; nf < 4; nf++) IMMA(accX[mi][nf], a1[mi], b0[nf]);
            #pragma unroll
            for (int mi = 0; mi < 2; mi++)
                #pragma unroll
                for (int nf = 0; nf < 4; nf++) IMMA(accX[mi][nf], a0[mi], b1[nf]);
        }
    }

    // ---- Fused epilogue ----
    // Rows: shuffle-reduce then RED straight to global (g_rpos sized MPAD: pad rows
    // receive exact-zero adds, never read). Cols: smem combine (4x dedup) then flush.
    float tmax = -CUDART_INF_F;
    const bool tmax_ok = (bm < NBM - 1) || (wm < 2);

    #pragma unroll
    for (int mi = 0; mi < 2; mi++) {
        #pragma unroll
        for (int h = 0; h < 2; h++) {
            float rp = 0.f, rn = 0.f;
            #pragma unroll
            for (int nf = 0; nf < 4; nf++) {
                float v0 = (float)acc11[mi][nf][2 * h] * 16384.f + (float)accX[mi][nf][2 * h] * 128.f;
                float v1 = (float)acc11[mi][nf][2 * h + 1] * 16384.f + (float)accX[mi][nf][2 * h + 1] * 128.f;
                rp += fmaxf(v0, 0.f) + fmaxf(v1, 0.f);
                rn += fmaxf(-v0, 0.f) + fmaxf(-v1, 0.f);
                tmax = fmaxf(tmax, fmaxf(v0, v1));
            }
            rp += __shfl_xor_sync(0xffffffffu, rp, 1); rp += __shfl_xor_sync(0xffffffffu, rp, 2);
            rn += __shfl_xor_sync(0xffffffffu, rn, 1); rn += __shfl_xor_sync(0xffffffffu, rn, 2);
            if ((lane & 3) == 0) {
                int gr = bm * 128 + wm * 32 + mi * 16 + (lane >> 2) + h * 8;
                atomicAdd(&g_rpos[gr], rp);
                atomicAdd(&g_rneg[gr], rn);
            }
        }
    }
    #pragma unroll
    for (int nf = 0; nf < 4; nf++) {
        #pragma unroll
        for (int j = 0; j < 2; j++) {
            float cp = 0.f, cn = 0.f;
            #pragma unroll
            for (int mi = 0; mi < 2; mi++) {
                float v0 = (float)acc11[mi][nf][j] * 16384.f + (float)accX[mi][nf][j] * 128.f;
                float v1 = (float)acc11[mi][nf][j + 2] * 16384.f + (float)accX[mi][nf][j + 2] * 128.f;
                cp += fmaxf(v0, 0.f) + fmaxf(v1, 0.f);
                cn += fmaxf(-v0, 0.f) + fmaxf(-v1, 0.f);
            }
            cp += __shfl_xor_sync(0xffffffffu, cp, 4);
            cp += __shfl_xor_sync(0xffffffffu, cp, 8);
            cp += __shfl_xor_sync(0xffffffffu, cp, 16);
            cn += __shfl_xor_sync(0xffffffffu, cn, 4);
            cn += __shfl_xor_sync(0xffffffffu, cn, 8);
            cn += __shfl_xor_sync(0xffffffffu, cn, 16);
            if (lane < 4) {
                int c = wn * 32 + nf * 8 + lane * 2 + j;
                atomicAdd(&s_cp[c], cp);
                atomicAdd(&s_cn[c], cn);
            }
        }
    }
    if (!tmax_ok) tmax = -CUDART_INF_F;
    #pragma unroll
    for (int off = 16; off; off >>= 1)
        tmax = fmaxf(tmax, __shfl_xor_sync(0xffffffffu, tmax, off));
    if (lane == 0) s_wmax[wid] = tmax;
    __syncthreads();

    if (tid < 64) {
        atomicAdd(&g_cpos[bn * 64 + tid], s_cp[tid]);
        atomicAdd(&g_cneg[bn * 64 + tid], s_cn[tid]);
    }
    if (tid == 0) {
        float bmax = s_wmax[0];
        #pragma unroll
        for (int w = 1; w < 8; w++) bmax = fmaxf(bmax, s_wmax[w]);
        atomicMax(&g_maxkey, fkey(bmax));
    }
}

// Bilinear resize (align_corners=False) with deferred 1/|M| scale + pos/neg selection.
// Also resets the prep barrier counter for the next graph replay.
__global__ void simcam_resize(float* __restrict__ out, int total) {
    int idx = blockIdx.x * blockDim.x + threadIdx.x;
    if (idx == 0) g_ctr = 0u;
    if (idx >= total) return;
    int p   = idx / (OUT_H * OUT_W);
    int rem = idx % (OUT_H * OUT_W);
    int oy  = rem / OUT_W;
    int ox  = rem % OUT_W;

    float Mv = unfkey(g_maxkey);
    const float* src;
    float inv;
    if (Mv > 0.f)      { src = (p == 0) ? g_rpos : g_cpos; inv =  1.0f / Mv; }
    else if (Mv < 0.f) { src = (p == 0) ? g_rneg : g_cneg; inv = -1.0f / Mv; }
    else               { src = (p == 0) ? g_rpos : g_cpos; inv = 0.0f; }

    const float s = 72.0f / 224.0f;
    float ys = fmaxf(((float)oy + 0.5f) * s - 0.5f, 0.0f);
    float xs = fmaxf(((float)ox + 0.5f) * s - 0.5f, 0.0f);
    int y0 = (int)floorf(ys), x0 = (int)floorf(xs);
    int y1 = min(y0 + 1, 71), x1 = min(x0 + 1, 71);
    float wy = ys - (float)y0, wx = xs - (float)x0;

    float a = src[y0 * 72 + x0], b = src[y0 * 72 + x1];
    float c = src[y1 * 72 + x0], d = src[y1 * 72 + x1];
    out[idx] = (a * (1.f - wy) * (1.f - wx) + b * (1.f - wy) * wx
              + c * wy * (1.f - wx)         + d * wy * wx) * inv;
}

extern "C" void kernel_launch(void* const* d_in, const int* in_sizes, int n_in,
                              void* d_out, int out_size) {
    const float* x = (const float*)d_in[0];   // (2,72,72,256) fp32
    cudaFuncSetAttribute(simcam_gemm, cudaFuncAttributeMaxDynamicSharedMemorySize, DYN_SMEM);

    simcam_prep<<<NPREP, 256>>>(x);
    dim3 grid(NBN, NBM);
    simcam_gemm<<<grid, 256, DYN_SMEM>>>();
    simcam_resize<<<(out_size + 255) / 256, 256>>>((float*)d_out, out_size);
}